// round 3
// baseline (speedup 1.0000x reference)
#include <cuda_runtime.h>
#include <math.h>

#define NB   2048
#define NT   200
#define NE   64
#define NH1  64
#define NH2  16
#define NROWS (NB*NT)

typedef unsigned long long u64;

__device__ __forceinline__ u64 fma2(u64 a, u64 b, u64 c) {
    u64 d;
    asm("fma.rn.f32x2 %0, %1, %2, %3;" : "=l"(d) : "l"(a), "l"(b), "l"(c));
    return d;
}
__device__ __forceinline__ float lo2(u64 v) { float a, b; asm("mov.b64 {%0,%1}, %2;" : "=f"(a), "=f"(b) : "l"(v)); return a; }
__device__ __forceinline__ float hi2(u64 v) { float a, b; asm("mov.b64 {%0,%1}, %2;" : "=f"(a), "=f"(b) : "l"(v)); return b; }
__device__ __forceinline__ float sum2(u64 v) { float a, b; asm("mov.b64 {%0,%1}, %2;" : "=f"(a), "=f"(b) : "l"(v)); return a + b; }
__device__ __forceinline__ u64 pack2(float a, float b) { u64 d; asm("mov.b64 %0, {%1,%2};" : "=l"(d) : "f"(a), "f"(b)); return d; }

// Scratch (device globals; no allocation allowed)
__device__ float g_x1[(size_t)NROWS * NH1];   // [B*T, 64]
__device__ float g_x2[(size_t)NROWS * NH2];   // [B*T, 16]
__device__ float g_sum1[NH1], g_sq1[NH1], g_mean1[NH1], g_rstd1[NH1];
__device__ float g_sum2[NH2], g_sq2[NH2], g_mean2[NH2], g_rstd2[NH2];

__global__ void k_zero() {
    int i = threadIdx.x;
    if (i < NH1) { g_sum1[i] = 0.f; g_sq1[i] = 0.f; }
    if (i < NH2) { g_sum2[i] = 0.f; g_sq2[i] = 0.f; }
}

// ---------------------------------------------------------------------------
// Kernel A: x1[b] = h[b] @ Wb(b) + cb(b);  per-feature sum/sumsq accumulate.
// Wb[e,j] = W1[64+e,j] - W1[128+e,j] + q[e]*W1[192+e,j]
// cb[j]   = b1[j] + sum_e q[e]*(W1[e,j] + W1[128+e,j])
// 512 threads: tx(8) -> 8 j-cols, ty(64) -> rows ty+64k (k<3, +1 if ty<8).
// K packed in f32x2 pairs; Wb stored transposed [j][e] with chunk^tx swizzle
// so ulonglong2 loads are 16B-aligned and conflict-free.
// ---------------------------------------------------------------------------
__global__ __launch_bounds__(512, 1) void k_gemm1(
    const float* __restrict__ q, const float* __restrict__ hist,
    const float* __restrict__ W1, const float* __restrict__ b1)
{
    __shared__ float s_q[NE];
    __shared__ float s_cb[NH1];
    __shared__ __align__(16) float s_WbT[64*64];     // [j][e], swizzled chunks
    __shared__ __align__(16) float s_h[NT][36];      // 32-wide e-chunk
    __shared__ float s_sum[NH1], s_sq[NH1];

    int b = blockIdx.x, tid = threadIdx.x;
    if (tid < NE) { s_q[tid] = q[b*NE + tid]; s_sum[tid] = 0.f; s_sq[tid] = 0.f; }
    __syncthreads();

    // Build swizzled WbT: logical [j][e] at float offset j*64 + ((e/4 ^ (j>>3&7))*4 + e%4)
    #pragma unroll
    for (int i = 0; i < 8; i++) {
        int idx = tid + 512*i;
        int e = idx >> 6, j = idx & 63;
        float v = W1[(64+e)*64 + j] - W1[(128+e)*64 + j] + s_q[e]*W1[(192+e)*64 + j];
        s_WbT[j*64 + ((((e>>2) ^ ((j>>3)&7)) << 2) | (e & 3))] = v;
    }
    if (tid < NH1) {
        float acc = b1[tid];
        #pragma unroll 8
        for (int e = 0; e < NE; e++)
            acc += s_q[e] * (W1[e*64 + tid] + W1[(128+e)*64 + tid]);
        s_cb[tid] = acc;
    }

    int tx = tid & 7, ty = tid >> 3;
    int j0 = tx * 8;
    bool has4 = (ty < 8);                       // rows 192..199

    u64 accp[4][8];                             // [row][j], e-pairs packed
    #pragma unroll
    for (int k = 0; k < 4; k++)
        #pragma unroll
        for (int jj = 0; jj < 8; jj++) accp[k][jj] = 0ull;

    for (int c = 0; c < 2; c++) {
        __syncthreads();
        // stage 200 x 32 chunk of h
        #pragma unroll
        for (int i = 0; i < 4; i++) {
            int f4 = tid + 512*i;
            if (f4 < 1600) {
                int t = f4 >> 3, e0 = (f4 & 7) << 2;
                *(float4*)&s_h[t][e0] =
                    *(const float4*)&hist[((size_t)(b*NT + t))*NE + c*32 + e0];
            }
        }
        __syncthreads();

        #pragma unroll
        for (int eo = 0; eo < 32; eo += 4) {
            int g = (c*32 + eo) >> 2;           // logical chunk 0..15
            ulonglong2 hp[4];
            #pragma unroll
            for (int k = 0; k < 3; k++)
                hp[k] = *(const ulonglong2*)&s_h[ty + 64*k][eo];
            if (has4) hp[3] = *(const ulonglong2*)&s_h[192 + ty][eo];
            #pragma unroll
            for (int jj = 0; jj < 8; jj++) {
                ulonglong2 wp = *(const ulonglong2*)&s_WbT[(j0+jj)*64 + ((g ^ tx) << 2)];
                #pragma unroll
                for (int k = 0; k < 3; k++) {
                    accp[k][jj] = fma2(hp[k].x, wp.x, accp[k][jj]);
                    accp[k][jj] = fma2(hp[k].y, wp.y, accp[k][jj]);
                }
                if (has4) {
                    accp[3][jj] = fma2(hp[3].x, wp.x, accp[3][jj]);
                    accp[3][jj] = fma2(hp[3].y, wp.y, accp[3][jj]);
                }
            }
        }
    }

    // epilogue: collapse pairs, bias add, stats, single write-out
    float lsum[8], lsq[8];
    #pragma unroll
    for (int jj = 0; jj < 8; jj++) { lsum[jj] = 0.f; lsq[jj] = 0.f; }

    #pragma unroll
    for (int k = 0; k < 4; k++) {
        if (k == 3 && !has4) break;
        int t = ty + 64*k;
        float v[8];
        #pragma unroll
        for (int jj = 0; jj < 8; jj++) {
            v[jj] = sum2(accp[k][jj]) + s_cb[j0 + jj];
            lsum[jj] += v[jj];
            lsq[jj]  += v[jj]*v[jj];
        }
        *(float4*)&g_x1[(size_t)(b*NT + t)*NH1 + j0]     = make_float4(v[0],v[1],v[2],v[3]);
        *(float4*)&g_x1[(size_t)(b*NT + t)*NH1 + j0 + 4] = make_float4(v[4],v[5],v[6],v[7]);
    }

    // reduce across ty within warp (lane bits 3,4), tx preserved
    #pragma unroll
    for (int jj = 0; jj < 8; jj++) {
        #pragma unroll
        for (int off = 8; off <= 16; off <<= 1) {
            lsum[jj] += __shfl_xor_sync(0xffffffffu, lsum[jj], off);
            lsq[jj]  += __shfl_xor_sync(0xffffffffu, lsq[jj],  off);
        }
    }
    if ((tid & 31) < 8) {
        int jb = (tid & 7) * 8;
        #pragma unroll
        for (int jj = 0; jj < 8; jj++) {
            atomicAdd(&s_sum[jb+jj], lsum[jj]);
            atomicAdd(&s_sq[jb+jj],  lsq[jj]);
        }
    }
    __syncthreads();
    if (tid < NH1) {
        atomicAdd(&g_sum1[tid], s_sum[tid]);
        atomicAdd(&g_sq1[tid],  s_sq[tid]);
    }
}

__global__ void k_fin1() {
    int j = threadIdx.x;
    if (j < NH1) {
        float n = (float)NROWS;
        float m = g_sum1[j] / n;
        float v = g_sq1[j] / n - m*m;
        g_mean1[j] = m;
        g_rstd1[j] = rsqrtf(v + 1e-8f);
    }
}

// ---------------------------------------------------------------------------
// Kernel B: x2 = dice1(x1) @ W2 + b2;  layer-2 stats.
// 256 rows/block, 256 threads: tx(4) -> 4 cols, rt(64) -> rows rt+64k.
// K packed f32x2; W2 stored transposed [c][e].
// ---------------------------------------------------------------------------
__global__ __launch_bounds__(256, 4) void k_gemm2(
    const float* __restrict__ W2, const float* __restrict__ b2,
    const float* __restrict__ alpha1)
{
    __shared__ __align__(16) float s_x[256][36];     // 32-wide e-chunk
    __shared__ __align__(16) float s_W2T[16][68];    // [c][e]
    __shared__ float s_m1[64], s_r1[64], s_a1[64], s_b2[16];
    __shared__ float s_sum[16], s_sq[16];

    int tid = threadIdx.x;
    int row0 = blockIdx.x * 256;
    if (tid < 64) { s_m1[tid] = g_mean1[tid]; s_r1[tid] = g_rstd1[tid]; s_a1[tid] = alpha1[tid]; }
    if (tid < 16) { s_b2[tid] = b2[tid]; s_sum[tid] = 0.f; s_sq[tid] = 0.f; }
    #pragma unroll
    for (int i = 0; i < 4; i++) {
        int idx = tid + 256*i;
        int e = idx >> 4, cc = idx & 15;
        s_W2T[cc][e] = W2[idx];
    }

    int tx = tid & 3, rt = tid >> 2;
    int c0 = tx * 4;
    u64 accp[4][4];                                  // [rowk][col], e-pairs
    #pragma unroll
    for (int k = 0; k < 4; k++)
        #pragma unroll
        for (int cc = 0; cc < 4; cc++) accp[k][cc] = 0ull;

    for (int c = 0; c < 2; c++) {
        __syncthreads();
        // stage 256x32 x1 chunk with dice1 applied
        #pragma unroll
        for (int i = 0; i < 8; i++) {
            int f4 = tid + 256*i;
            int r = f4 >> 3, e0 = (f4 & 7) << 2;
            float4 v = *(const float4*)&g_x1[(size_t)(row0 + r)*64 + c*32 + e0];
            float vv[4] = {v.x, v.y, v.z, v.w};
            #pragma unroll
            for (int u = 0; u < 4; u++) {
                int j = c*32 + e0 + u;
                float xn = (vv[u] - s_m1[j]) * s_r1[j];
                float p  = __fdividef(1.f, 1.f + __expf(-xn));
                float a  = s_a1[j];
                vv[u] = vv[u] * (a + (1.f - a) * p);
            }
            *(float4*)&s_x[r][e0] = make_float4(vv[0], vv[1], vv[2], vv[3]);
        }
        __syncthreads();

        #pragma unroll
        for (int eo = 0; eo < 32; eo += 4) {
            ulonglong2 wp[4];
            #pragma unroll
            for (int cc = 0; cc < 4; cc++)
                wp[cc] = *(const ulonglong2*)&s_W2T[c0+cc][c*32 + eo];
            #pragma unroll
            for (int k = 0; k < 4; k++) {
                ulonglong2 xp = *(const ulonglong2*)&s_x[rt + 64*k][eo];
                #pragma unroll
                for (int cc = 0; cc < 4; cc++) {
                    accp[k][cc] = fma2(xp.x, wp[cc].x, accp[k][cc]);
                    accp[k][cc] = fma2(xp.y, wp[cc].y, accp[k][cc]);
                }
            }
        }
    }

    float lps[4] = {0.f,0.f,0.f,0.f}, lpq[4] = {0.f,0.f,0.f,0.f};
    #pragma unroll
    for (int k = 0; k < 4; k++) {
        float v[4];
        #pragma unroll
        for (int cc = 0; cc < 4; cc++) {
            v[cc] = sum2(accp[k][cc]) + s_b2[c0+cc];
            lps[cc] += v[cc];
            lpq[cc] += v[cc]*v[cc];
        }
        *(float4*)&g_x2[(size_t)(row0 + rt + 64*k)*16 + c0] = make_float4(v[0],v[1],v[2],v[3]);
    }
    // reduce across rt within warp (lane bits 2,3,4), tx preserved
    #pragma unroll
    for (int cc = 0; cc < 4; cc++) {
        #pragma unroll
        for (int off = 4; off <= 16; off <<= 1) {
            lps[cc] += __shfl_xor_sync(0xffffffffu, lps[cc], off);
            lpq[cc] += __shfl_xor_sync(0xffffffffu, lpq[cc], off);
        }
    }
    if ((tid & 31) < 4) {
        int cb = (tid & 3) * 4;
        #pragma unroll
        for (int cc = 0; cc < 4; cc++) {
            atomicAdd(&s_sum[cb+cc], lps[cc]);
            atomicAdd(&s_sq[cb+cc],  lpq[cc]);
        }
    }
    __syncthreads();
    if (tid < 16) {
        atomicAdd(&g_sum2[tid], s_sum[tid]);
        atomicAdd(&g_sq2[tid],  s_sq[tid]);
    }
}

__global__ void k_fin2() {
    int j = threadIdx.x;
    if (j < NH2) {
        float n = (float)NROWS;
        float m = g_sum2[j] / n;
        float v = g_sq2[j] / n - m*m;
        g_mean2[j] = m;
        g_rstd2[j] = rsqrtf(v + 1e-8f);
    }
}

// ---------------------------------------------------------------------------
// Kernel C: dice2 -> mask -> softmax over T (per h) -> score @ hist -> out
// One block per batch; h-pairs packed in epilogue.
// ---------------------------------------------------------------------------
__global__ __launch_bounds__(256, 4) void k_final(
    const float* __restrict__ hist, const int* __restrict__ lens,
    const float* __restrict__ alpha2, float* __restrict__ out)
{
    __shared__ __align__(16) float s_logit[200][20];
    __shared__ __align__(16) float s_hist[50][64];
    __shared__ float s_inv[16];
    __shared__ float s_m2[16], s_r2[16], s_a2[16];

    int b = blockIdx.x, tid = threadIdx.x;
    if (tid < 16) { s_m2[tid] = g_mean2[tid]; s_r2[tid] = g_rstd2[tid]; s_a2[tid] = alpha2[tid]; }
    __syncthreads();
    int len = lens[b];

    // stage logits with dice2 + mask (mask: t < len -> 1e-9)
    #pragma unroll
    for (int i = 0; i < 4; i++) {
        int f4 = tid + 256*i;
        if (f4 < 800) {
            int r = f4 >> 2, h0 = (f4 & 3) << 2;
            float4 v = *(const float4*)&g_x2[(size_t)(b*NT + r)*16 + h0];
            float vv[4] = {v.x, v.y, v.z, v.w};
            #pragma unroll
            for (int u = 0; u < 4; u++) {
                int hh = h0 + u;
                float xn = (vv[u] - s_m2[hh]) * s_r2[hh];
                float p  = __fdividef(1.f, 1.f + __expf(-xn));
                float a  = s_a2[hh];
                float d  = vv[u] * (a + (1.f - a) * p);
                vv[u] = (r < len) ? 1e-9f : d;
            }
            *(float4*)&s_logit[r][h0] = make_float4(vv[0], vv[1], vv[2], vv[3]);
        }
    }
    __syncthreads();

    // 16 softmaxes over T=200, one per half-warp-of-16
    int g = tid >> 4, l16 = tid & 15;
    float m = -1e30f;
    for (int t = l16; t < NT; t += 16) m = fmaxf(m, s_logit[t][g]);
    #pragma unroll
    for (int off = 1; off < 16; off <<= 1)
        m = fmaxf(m, __shfl_xor_sync(0xffffffffu, m, off, 16));
    float s = 0.f;
    for (int t = l16; t < NT; t += 16) {
        float ev = __expf(s_logit[t][g] - m);
        s_logit[t][g] = ev;
        s += ev;
    }
    #pragma unroll
    for (int off = 1; off < 16; off <<= 1)
        s += __shfl_xor_sync(0xffffffffu, s, off, 16);
    if (l16 == 0) s_inv[g] = __fdividef(1.f, s);

    // out[b,h,e] = (sum_t exp_t[h] * hist[b,t,e]) * inv[h]; h-pairs packed
    int e = tid & 63, hg = tid >> 6;
    u64 accp[2] = {0ull, 0ull};
    for (int tc = 0; tc < 4; tc++) {
        __syncthreads();
        #pragma unroll
        for (int i = 0; i < 4; i++) {
            int f4 = tid + 256*i;
            if (f4 < 800) {
                int tt = f4 >> 4, e0 = (f4 & 15) << 2;
                *(float4*)&s_hist[tt][e0] =
                    *(const float4*)&hist[(size_t)(b*NT + tc*50 + tt)*64 + e0];
            }
        }
        __syncthreads();
        #pragma unroll 2
        for (int t = 0; t < 50; t++) {
            ulonglong2 sc = *(const ulonglong2*)&s_logit[tc*50 + t][hg*4];
            float hv = s_hist[t][e];
            u64 hvp = pack2(hv, hv);
            accp[0] = fma2(hvp, sc.x, accp[0]);
            accp[1] = fma2(hvp, sc.y, accp[1]);
        }
    }
    float4 iv = *(const float4*)&s_inv[hg*4];
    out[(size_t)(b*NH2 + hg*4 + 0)*NE + e] = lo2(accp[0]) * iv.x;
    out[(size_t)(b*NH2 + hg*4 + 1)*NE + e] = hi2(accp[0]) * iv.y;
    out[(size_t)(b*NH2 + hg*4 + 2)*NE + e] = lo2(accp[1]) * iv.z;
    out[(size_t)(b*NH2 + hg*4 + 3)*NE + e] = hi2(accp[1]) * iv.w;
}

extern "C" void kernel_launch(void* const* d_in, const int* in_sizes, int n_in,
                              void* d_out, int out_size)
{
    const float* q    = (const float*)d_in[0];
    const float* hist = (const float*)d_in[1];
    const int*   lens = (const int*)  d_in[2];
    const float* W1   = (const float*)d_in[3];
    const float* b1   = (const float*)d_in[4];
    const float* a1   = (const float*)d_in[5];
    const float* W2   = (const float*)d_in[6];
    const float* b2   = (const float*)d_in[7];
    const float* a2   = (const float*)d_in[8];
    float* out = (float*)d_out;

    k_zero<<<1, 64>>>();
    k_gemm1<<<NB, 512>>>(q, hist, W1, b1);
    k_fin1<<<1, 64>>>();
    k_gemm2<<<NROWS/256, 256>>>(W2, b2, a1);
    k_fin2<<<1, 16>>>();
    k_final<<<NB, 256>>>(hist, lens, a2, out);
}

// round 4
// speedup vs baseline: 1.4993x; 1.4993x over previous
#include <cuda_runtime.h>
#include <math.h>

#define NB   2048
#define NT   200
#define NE   64
#define NH1  64
#define NH2  16
#define NROWS (NB*NT)

// Scratch (device globals; no allocation allowed)
__device__ float g_x1[(size_t)NROWS * NH1];   // [B*T, 64]
__device__ float g_x2[(size_t)NROWS * NH2];   // [B*T, 16]
__device__ float g_sum1[NH1], g_sq1[NH1], g_mean1[NH1], g_rstd1[NH1];
__device__ float g_sum2[NH2], g_sq2[NH2], g_mean2[NH2], g_rstd2[NH2];

__device__ __forceinline__ unsigned tf32_of(float f) {
    unsigned r;
    asm("cvt.rna.tf32.f32 %0, %1;" : "=r"(r) : "f"(f));
    return r;
}
// split a into tf32 hi + tf32 lo (a ~= hi + lo, ~22 effective mantissa bits)
__device__ __forceinline__ void tf32_split(float a, unsigned& hi, unsigned& lo) {
    hi = tf32_of(a);
    lo = tf32_of(a - __uint_as_float(hi));
}

#define MMA_TF32(d, a0,a1,a2,a3, b0,b1) \
    asm("mma.sync.aligned.m16n8k8.row.col.f32.tf32.tf32.f32 " \
        "{%0,%1,%2,%3}, {%4,%5,%6,%7}, {%8,%9}, {%0,%1,%2,%3};" \
        : "+f"(d[0]), "+f"(d[1]), "+f"(d[2]), "+f"(d[3]) \
        : "r"(a0), "r"(a1), "r"(a2), "r"(a3), "r"(b0), "r"(b1))

__global__ void k_zero() {
    int i = threadIdx.x;
    if (i < NH1) { g_sum1[i] = 0.f; g_sq1[i] = 0.f; }
    if (i < NH2) { g_sum2[i] = 0.f; g_sq2[i] = 0.f; }
}

// ---------------------------------------------------------------------------
// Kernel A: x1[b] = h[b] @ Wb(b) + cb(b)  via 3xTF32 mma.sync.
// Wb[e,j] = W1[64+e,j] - W1[128+e,j] + q[e]*W1[192+e,j]   (split hi/lo in smem)
// cb[j]   = b1[j] + sum_e q[e]*(W1[e,j] + W1[128+e,j])
// 512 threads; warps 0..12 each own one 16-row m-tile (rows padded to 208).
// ---------------------------------------------------------------------------
__global__ __launch_bounds__(512, 2) void k_gemm1(
    const float* __restrict__ q, const float* __restrict__ hist,
    const float* __restrict__ W1, const float* __restrict__ b1)
{
    extern __shared__ __align__(16) float dsm[];
    float* s_h   = dsm;                       // [208][68] fp32 hist tile
    float* s_WbH = dsm + 208*68;              // [64][72] tf32-hi of Wb (K-major)
    float* s_WbL = s_WbH + 64*72;             // [64][72] tf32-lo
    __shared__ float s_q[NE], s_cb[NH1], s_sum[NH1], s_sq[NH1];

    int b = blockIdx.x, tid = threadIdx.x;
    if (tid < NE) { s_q[tid] = q[b*NE + tid]; s_sum[tid] = 0.f; s_sq[tid] = 0.f; }
    __syncthreads();

    // Build Wb and split to tf32 hi/lo planes
    #pragma unroll
    for (int i = 0; i < 8; i++) {
        int idx = tid + 512*i;
        int e = idx >> 6, j = idx & 63;
        float w = W1[(64+e)*64 + j] - W1[(128+e)*64 + j] + s_q[e]*W1[(192+e)*64 + j];
        unsigned wh, wl; tf32_split(w, wh, wl);
        s_WbH[e*72 + j] = __uint_as_float(wh);
        s_WbL[e*72 + j] = __uint_as_float(wl);
    }
    if (tid < NH1) {
        float acc = b1[tid];
        #pragma unroll 8
        for (int e = 0; e < NE; e++)
            acc += s_q[e] * (W1[e*64 + tid] + W1[(128+e)*64 + tid]);
        s_cb[tid] = acc;
    }
    // Stage hist tile (fp32), zero the 8 pad rows
    #pragma unroll
    for (int i = 0; i < 7; i++) {
        int f4 = tid + 512*i;
        if (f4 < 3200) {
            int t = f4 >> 4, e0 = (f4 & 15) << 2;
            *(float4*)&s_h[t*68 + e0] =
                *(const float4*)&hist[((size_t)(b*NT + t))*NE + e0];
        }
    }
    if (tid < 544) s_h[200*68 + tid] = 0.f;
    __syncthreads();

    int w = tid >> 5, lane = tid & 31, g = lane >> 2, tin = lane & 3;
    if (w < 13) {
        float d[8][4];
        #pragma unroll
        for (int j = 0; j < 8; j++)
            #pragma unroll
            for (int u = 0; u < 4; u++) d[j][u] = 0.f;

        int arow = (16*w + g)*68;
        #pragma unroll
        for (int kt = 0; kt < 8; kt++) {
            int k0 = kt*8;
            float a0f = s_h[arow + k0 + tin];
            float a1f = s_h[arow + 8*68 + k0 + tin];
            float a2f = s_h[arow + k0 + tin + 4];
            float a3f = s_h[arow + 8*68 + k0 + tin + 4];
            unsigned ah0,ah1,ah2,ah3, al0,al1,al2,al3;
            tf32_split(a0f, ah0, al0); tf32_split(a1f, ah1, al1);
            tf32_split(a2f, ah2, al2); tf32_split(a3f, ah3, al3);
            int bbase = (k0 + tin)*72 + g;
            #pragma unroll
            for (int j = 0; j < 8; j++) {
                unsigned bh0 = __float_as_uint(s_WbH[bbase + j*8]);
                unsigned bh1 = __float_as_uint(s_WbH[bbase + 4*72 + j*8]);
                unsigned bl0 = __float_as_uint(s_WbL[bbase + j*8]);
                unsigned bl1 = __float_as_uint(s_WbL[bbase + 4*72 + j*8]);
                MMA_TF32(d[j], ah0,ah1,ah2,ah3, bh0,bh1);
                MMA_TF32(d[j], ah0,ah1,ah2,ah3, bl0,bl1);
                MMA_TF32(d[j], al0,al1,al2,al3, bh0,bh1);
            }
        }

        // epilogue: bias, store, stats
        int rA = 16*w + g, rB = rA + 8;
        #pragma unroll
        for (int j = 0; j < 8; j++) {
            int c0 = j*8 + tin*2;
            float cb0 = s_cb[c0], cb1 = s_cb[c0+1];
            float v0 = d[j][0] + cb0, v1 = d[j][1] + cb1;
            float v2 = d[j][2] + cb0, v3 = d[j][3] + cb1;
            float sc0 = v0, sc1 = v1, qc0 = v0*v0, qc1 = v1*v1;
            *(float2*)&g_x1[(size_t)(b*NT + rA)*NH1 + c0] = make_float2(v0, v1);
            if (rB < NT) {
                *(float2*)&g_x1[(size_t)(b*NT + rB)*NH1 + c0] = make_float2(v2, v3);
                sc0 += v2; sc1 += v3; qc0 += v2*v2; qc1 += v3*v3;
            }
            #pragma unroll
            for (int off = 4; off <= 16; off <<= 1) {
                sc0 += __shfl_xor_sync(0xffffffffu, sc0, off);
                sc1 += __shfl_xor_sync(0xffffffffu, sc1, off);
                qc0 += __shfl_xor_sync(0xffffffffu, qc0, off);
                qc1 += __shfl_xor_sync(0xffffffffu, qc1, off);
            }
            if (lane < 4) {
                atomicAdd(&s_sum[c0],   sc0); atomicAdd(&s_sum[c0+1], sc1);
                atomicAdd(&s_sq[c0],    qc0); atomicAdd(&s_sq[c0+1],  qc1);
            }
        }
    }
    __syncthreads();
    if (tid < NH1) {
        atomicAdd(&g_sum1[tid], s_sum[tid]);
        atomicAdd(&g_sq1[tid],  s_sq[tid]);
    }
}

__global__ void k_fin1() {
    int j = threadIdx.x;
    if (j < NH1) {
        float n = (float)NROWS;
        float m = g_sum1[j] / n;
        float v = g_sq1[j] / n - m*m;
        g_mean1[j] = m;
        g_rstd1[j] = rsqrtf(v + 1e-8f);
    }
}

// ---------------------------------------------------------------------------
// Kernel B: x2 = dice1(x1) @ W2 + b2 via 3xTF32 mma.sync; layer-2 stats.
// 128 rows/block, 256 threads, 8 warps (one 16-row m-tile each).
// ---------------------------------------------------------------------------
__global__ __launch_bounds__(256, 4) void k_gemm2(
    const float* __restrict__ W2, const float* __restrict__ b2,
    const float* __restrict__ alpha1)
{
    __shared__ __align__(16) float s_x[128*68];     // fp32 dice1(x1) tile
    __shared__ float s_W2TH[16*68], s_W2TL[16*68];  // W2^T hi/lo [n][k]
    __shared__ float s_m1[64], s_r1[64], s_a1[64], s_b2[16];
    __shared__ float s_sum[16], s_sq[16];

    int tid = threadIdx.x;
    int row0 = blockIdx.x * 128;
    if (tid < 64) { s_m1[tid] = g_mean1[tid]; s_r1[tid] = g_rstd1[tid]; s_a1[tid] = alpha1[tid]; }
    if (tid < 16) { s_b2[tid] = b2[tid]; s_sum[tid] = 0.f; s_sq[tid] = 0.f; }
    #pragma unroll
    for (int i = 0; i < 4; i++) {
        int idx = tid + 256*i;
        int k = idx >> 4, n = idx & 15;
        float wv = W2[idx];
        unsigned wh, wl; tf32_split(wv, wh, wl);
        s_W2TH[n*68 + k] = __uint_as_float(wh);
        s_W2TL[n*68 + k] = __uint_as_float(wl);
    }
    __syncthreads();

    // stage 128x64 x1 tile with dice1 applied
    #pragma unroll 2
    for (int i = 0; i < 8; i++) {
        int f4 = tid + 256*i;
        int r = f4 >> 4, e0 = (f4 & 15) << 2;
        float4 v = *(const float4*)&g_x1[(size_t)(row0 + r)*64 + e0];
        float vv[4] = {v.x, v.y, v.z, v.w};
        #pragma unroll
        for (int u = 0; u < 4; u++) {
            int j = e0 + u;
            float xn = (vv[u] - s_m1[j]) * s_r1[j];
            float p  = __fdividef(1.f, 1.f + __expf(-xn));
            float a  = s_a1[j];
            vv[u] = vv[u] * (a + (1.f - a) * p);
        }
        *(float4*)&s_x[r*68 + e0] = make_float4(vv[0], vv[1], vv[2], vv[3]);
    }
    __syncthreads();

    int w = tid >> 5, lane = tid & 31, g = lane >> 2, tin = lane & 3;
    float d[2][4];
    #pragma unroll
    for (int n = 0; n < 2; n++)
        #pragma unroll
        for (int u = 0; u < 4; u++) d[n][u] = 0.f;

    int arow = (16*w + g)*68;
    #pragma unroll
    for (int kt = 0; kt < 8; kt++) {
        int k0 = kt*8;
        float a0f = s_x[arow + k0 + tin];
        float a1f = s_x[arow + 8*68 + k0 + tin];
        float a2f = s_x[arow + k0 + tin + 4];
        float a3f = s_x[arow + 8*68 + k0 + tin + 4];
        unsigned ah0,ah1,ah2,ah3, al0,al1,al2,al3;
        tf32_split(a0f, ah0, al0); tf32_split(a1f, ah1, al1);
        tf32_split(a2f, ah2, al2); tf32_split(a3f, ah3, al3);
        #pragma unroll
        for (int n = 0; n < 2; n++) {
            int bbase = (n*8 + g)*68 + k0 + tin;
            unsigned bh0 = __float_as_uint(s_W2TH[bbase]);
            unsigned bh1 = __float_as_uint(s_W2TH[bbase + 4]);
            unsigned bl0 = __float_as_uint(s_W2TL[bbase]);
            unsigned bl1 = __float_as_uint(s_W2TL[bbase + 4]);
            MMA_TF32(d[n], ah0,ah1,ah2,ah3, bh0,bh1);
            MMA_TF32(d[n], ah0,ah1,ah2,ah3, bl0,bl1);
            MMA_TF32(d[n], al0,al1,al2,al3, bh0,bh1);
        }
    }

    int rA = 16*w + g, rB = rA + 8;
    #pragma unroll
    for (int n = 0; n < 2; n++) {
        int c0 = n*8 + tin*2;
        float b0v = s_b2[c0], b1v = s_b2[c0+1];
        float v0 = d[n][0] + b0v, v1 = d[n][1] + b1v;
        float v2 = d[n][2] + b0v, v3 = d[n][3] + b1v;
        *(float2*)&g_x2[(size_t)(row0 + rA)*16 + c0] = make_float2(v0, v1);
        *(float2*)&g_x2[(size_t)(row0 + rB)*16 + c0] = make_float2(v2, v3);
        float sc0 = v0 + v2, sc1 = v1 + v3;
        float qc0 = v0*v0 + v2*v2, qc1 = v1*v1 + v3*v3;
        #pragma unroll
        for (int off = 4; off <= 16; off <<= 1) {
            sc0 += __shfl_xor_sync(0xffffffffu, sc0, off);
            sc1 += __shfl_xor_sync(0xffffffffu, sc1, off);
            qc0 += __shfl_xor_sync(0xffffffffu, qc0, off);
            qc1 += __shfl_xor_sync(0xffffffffu, qc1, off);
        }
        if (lane < 4) {
            atomicAdd(&s_sum[c0],   sc0); atomicAdd(&s_sum[c0+1], sc1);
            atomicAdd(&s_sq[c0],    qc0); atomicAdd(&s_sq[c0+1],  qc1);
        }
    }
    __syncthreads();
    if (tid < 16) {
        atomicAdd(&g_sum2[tid], s_sum[tid]);
        atomicAdd(&g_sq2[tid],  s_sq[tid]);
    }
}

__global__ void k_fin2() {
    int j = threadIdx.x;
    if (j < NH2) {
        float n = (float)NROWS;
        float m = g_sum2[j] / n;
        float v = g_sq2[j] / n - m*m;
        g_mean2[j] = m;
        g_rstd2[j] = rsqrtf(v + 1e-8f);
    }
}

// ---------------------------------------------------------------------------
// Kernel C: dice2 -> mask -> softmax over T (per h) -> score @ hist -> out
// One block per batch (round-2 scalar version).
// ---------------------------------------------------------------------------
__global__ __launch_bounds__(256, 4) void k_final(
    const float* __restrict__ hist, const int* __restrict__ lens,
    const float* __restrict__ alpha2, float* __restrict__ out)
{
    __shared__ __align__(16) float s_logit[200][20];
    __shared__ __align__(16) float s_hist[50][64];
    __shared__ float s_inv[16];
    __shared__ float s_m2[16], s_r2[16], s_a2[16];

    int b = blockIdx.x, tid = threadIdx.x;
    if (tid < 16) { s_m2[tid] = g_mean2[tid]; s_r2[tid] = g_rstd2[tid]; s_a2[tid] = alpha2[tid]; }
    __syncthreads();
    int len = lens[b];

    #pragma unroll
    for (int i = 0; i < 4; i++) {
        int f4 = tid + 256*i;
        if (f4 < 800) {
            int r = f4 >> 2, h0 = (f4 & 3) << 2;
            float4 v = *(const float4*)&g_x2[(size_t)(b*NT + r)*16 + h0];
            float vv[4] = {v.x, v.y, v.z, v.w};
            #pragma unroll
            for (int u = 0; u < 4; u++) {
                int hh = h0 + u;
                float xn = (vv[u] - s_m2[hh]) * s_r2[hh];
                float p  = __fdividef(1.f, 1.f + __expf(-xn));
                float a  = s_a2[hh];
                float dd = vv[u] * (a + (1.f - a) * p);
                vv[u] = (r < len) ? 1e-9f : dd;
            }
            *(float4*)&s_logit[r][h0] = make_float4(vv[0], vv[1], vv[2], vv[3]);
        }
    }
    __syncthreads();

    int g = tid >> 4, l16 = tid & 15;
    float m = -1e30f;
    for (int t = l16; t < NT; t += 16) m = fmaxf(m, s_logit[t][g]);
    #pragma unroll
    for (int off = 1; off < 16; off <<= 1)
        m = fmaxf(m, __shfl_xor_sync(0xffffffffu, m, off, 16));
    float s = 0.f;
    for (int t = l16; t < NT; t += 16) {
        float ev = __expf(s_logit[t][g] - m);
        s_logit[t][g] = ev;
        s += ev;
    }
    #pragma unroll
    for (int off = 1; off < 16; off <<= 1)
        s += __shfl_xor_sync(0xffffffffu, s, off, 16);
    if (l16 == 0) s_inv[g] = __fdividef(1.f, s);

    int e = tid & 63, hg = tid >> 6;
    float acc[4] = {0.f, 0.f, 0.f, 0.f};
    for (int tc = 0; tc < 4; tc++) {
        __syncthreads();
        #pragma unroll
        for (int i = 0; i < 4; i++) {
            int f4 = tid + 256*i;
            if (f4 < 800) {
                int tt = f4 >> 4, e0 = (f4 & 15) << 2;
                *(float4*)&s_hist[tt][e0] =
                    *(const float4*)&hist[(size_t)(b*NT + tc*50 + tt)*64 + e0];
            }
        }
        __syncthreads();
        #pragma unroll 2
        for (int t = 0; t < 50; t++) {
            float4 sc = *(const float4*)&s_logit[tc*50 + t][hg*4];
            float hv = s_hist[t][e];
            acc[0] = fmaf(sc.x, hv, acc[0]);
            acc[1] = fmaf(sc.y, hv, acc[1]);
            acc[2] = fmaf(sc.z, hv, acc[2]);
            acc[3] = fmaf(sc.w, hv, acc[3]);
        }
    }
    float4 iv = *(const float4*)&s_inv[hg*4];
    float ia[4] = {iv.x, iv.y, iv.z, iv.w};
    #pragma unroll
    for (int k = 0; k < 4; k++)
        out[(size_t)(b*NH2 + hg*4 + k)*NE + e] = acc[k] * ia[k];
}

extern "C" void kernel_launch(void* const* d_in, const int* in_sizes, int n_in,
                              void* d_out, int out_size)
{
    const float* q    = (const float*)d_in[0];
    const float* hist = (const float*)d_in[1];
    const int*   lens = (const int*)  d_in[2];
    const float* W1   = (const float*)d_in[3];
    const float* b1   = (const float*)d_in[4];
    const float* a1   = (const float*)d_in[5];
    const float* W2   = (const float*)d_in[6];
    const float* b2   = (const float*)d_in[7];
    const float* a2   = (const float*)d_in[8];
    float* out = (float*)d_out;

    const int dyn1 = (208*68 + 2*64*72) * 4;   // 93440 B
    static int s_attr_done = 0;
    if (!s_attr_done) {
        cudaFuncSetAttribute(k_gemm1, cudaFuncAttributeMaxDynamicSharedMemorySize, dyn1);
        s_attr_done = 1;
    }

    k_zero<<<1, 64>>>();
    k_gemm1<<<NB, 512, dyn1>>>(q, hist, W1, b1);
    k_fin1<<<1, 64>>>();
    k_gemm2<<<NROWS/128, 256>>>(W2, b2, a1);
    k_fin2<<<1, 16>>>();
    k_final<<<NB, 256>>>(hist, lens, a2, out);
}

// round 5
// speedup vs baseline: 1.5090x; 1.0065x over previous
#include <cuda_runtime.h>
#include <math.h>

#define NB   2048
#define NT   200
#define NE   64
#define NH1  64
#define NH2  16
#define NROWS (NB*NT)

// Scratch (device globals; no allocation allowed)
__device__ float g_x1[(size_t)NROWS * NH1];   // [B*T, 64]
__device__ float g_x2[(size_t)NROWS * NH2];   // [B*T, 16]
__device__ float g_sum1[NH1], g_sq1[NH1];
__device__ float g_sum2[NH2], g_sq2[NH2];

__device__ __forceinline__ unsigned tf32_of(float f) {
    unsigned r;
    asm("cvt.rna.tf32.f32 %0, %1;" : "=r"(r) : "f"(f));
    return r;
}
// split a into tf32 hi + tf32 lo (a ~= hi + lo, ~22 effective mantissa bits)
__device__ __forceinline__ void tf32_split(float a, unsigned& hi, unsigned& lo) {
    hi = tf32_of(a);
    lo = tf32_of(a - __uint_as_float(hi));
}

#define MMA_TF32(d, a0,a1,a2,a3, b0,b1) \
    asm("mma.sync.aligned.m16n8k8.row.col.f32.tf32.tf32.f32 " \
        "{%0,%1,%2,%3}, {%4,%5,%6,%7}, {%8,%9}, {%0,%1,%2,%3};" \
        : "+f"(d[0]), "+f"(d[1]), "+f"(d[2]), "+f"(d[3]) \
        : "r"(a0), "r"(a1), "r"(a2), "r"(a3), "r"(b0), "r"(b1))

__global__ void k_zero() {
    int i = threadIdx.x;
    if (i < NH1) { g_sum1[i] = 0.f; g_sq1[i] = 0.f; }
    if (i < NH2) { g_sum2[i] = 0.f; g_sq2[i] = 0.f; }
}

// ---------------------------------------------------------------------------
// Kernel A: x1[b] = h[b] @ Wb(b) + cb(b)  via 3xTF32 mma.sync.
// Wb[e,j] = W1[64+e,j] - W1[128+e,j] + q[e]*W1[192+e,j]   (split hi/lo in smem)
// cb[j]   = b1[j] + sum_e q[e]*(W1[e,j] + W1[128+e,j])    (parallel partials)
// 2 blocks per batch: block half 0 -> rows 0..127 (8 m-tiles),
//                     block half 1 -> rows 128..199 (5 m-tiles, 8 pad rows).
// 256 threads, 8 warps; 71.7KB dyn smem -> 3 blocks/SM.
// ---------------------------------------------------------------------------
__global__ __launch_bounds__(256, 3) void k_gemm1(
    const float* __restrict__ q, const float* __restrict__ hist,
    const float* __restrict__ W1, const float* __restrict__ b1)
{
    extern __shared__ __align__(16) float dsm[];
    float* s_h   = dsm;                       // [128][68] fp32 hist rows
    float* s_WbH = dsm + 128*68;              // [64][72] tf32-hi of Wb (K-major)
    float* s_WbL = s_WbH + 64*72;             // [64][72] tf32-lo
    __shared__ float s_q[NE], s_cb[NH1], s_sum[NH1], s_sq[NH1];

    int bid = blockIdx.x, tid = threadIdx.x;
    int b = bid >> 1, half = bid & 1;
    int R0 = half ? 128 : 0;
    int ntile = half ? 5 : 8;

    if (tid < NE) {
        s_q[tid] = q[b*NE + tid];
        s_cb[tid] = b1[tid];
        s_sum[tid] = 0.f; s_sq[tid] = 0.f;
    }
    __syncthreads();

    // Build Wb and split to tf32 hi/lo planes
    #pragma unroll
    for (int i = 0; i < 16; i++) {
        int idx = tid + 256*i;
        int e = idx >> 6, j = idx & 63;
        float w = W1[(64+e)*64 + j] - W1[(128+e)*64 + j] + s_q[e]*W1[(192+e)*64 + j];
        unsigned wh, wl; tf32_split(w, wh, wl);
        s_WbH[e*72 + j] = __uint_as_float(wh);
        s_WbL[e*72 + j] = __uint_as_float(wl);
    }
    // cb partial sums: 4 parts x 64 j = 256 threads
    {
        int j = tid & 63, part = tid >> 6;
        float acc = 0.f;
        #pragma unroll
        for (int i = 0; i < 16; i++) {
            int e = part*16 + i;
            acc += s_q[e] * (W1[e*64 + j] + W1[(128+e)*64 + j]);
        }
        atomicAdd(&s_cb[j], acc);
    }
    // Stage hist rows R0..R0+127 (zeros past NT)
    #pragma unroll
    for (int i = 0; i < 8; i++) {
        int f4 = tid + 256*i;
        int r = f4 >> 4, e0 = (f4 & 15) << 2;
        int t = R0 + r;
        float4 v = (t < NT) ? *(const float4*)&hist[((size_t)(b*NT + t))*NE + e0]
                            : make_float4(0.f, 0.f, 0.f, 0.f);
        *(float4*)&s_h[r*68 + e0] = v;
    }
    __syncthreads();

    int w = tid >> 5, lane = tid & 31, g = lane >> 2, tin = lane & 3;
    if (w < ntile) {
        float d[8][4];
        #pragma unroll
        for (int j = 0; j < 8; j++)
            #pragma unroll
            for (int u = 0; u < 4; u++) d[j][u] = 0.f;

        int arow = (16*w + g)*68;
        #pragma unroll
        for (int kt = 0; kt < 8; kt++) {
            int k0 = kt*8;
            float a0f = s_h[arow + k0 + tin];
            float a1f = s_h[arow + 8*68 + k0 + tin];
            float a2f = s_h[arow + k0 + tin + 4];
            float a3f = s_h[arow + 8*68 + k0 + tin + 4];
            unsigned ah0,ah1,ah2,ah3, al0,al1,al2,al3;
            tf32_split(a0f, ah0, al0); tf32_split(a1f, ah1, al1);
            tf32_split(a2f, ah2, al2); tf32_split(a3f, ah3, al3);
            int bbase = (k0 + tin)*72 + g;
            #pragma unroll
            for (int j = 0; j < 8; j++) {
                unsigned bh0 = __float_as_uint(s_WbH[bbase + j*8]);
                unsigned bh1 = __float_as_uint(s_WbH[bbase + 4*72 + j*8]);
                unsigned bl0 = __float_as_uint(s_WbL[bbase + j*8]);
                unsigned bl1 = __float_as_uint(s_WbL[bbase + 4*72 + j*8]);
                MMA_TF32(d[j], ah0,ah1,ah2,ah3, bh0,bh1);
                MMA_TF32(d[j], ah0,ah1,ah2,ah3, bl0,bl1);
                MMA_TF32(d[j], al0,al1,al2,al3, bh0,bh1);
            }
        }

        // epilogue: bias, store, stats
        int rA = R0 + 16*w + g, rB = rA + 8;
        bool okB = (rB < NT);
        #pragma unroll
        for (int j = 0; j < 8; j++) {
            int c0 = j*8 + tin*2;
            float cb0 = s_cb[c0], cb1 = s_cb[c0+1];
            float v0 = d[j][0] + cb0, v1 = d[j][1] + cb1;
            float v2 = d[j][2] + cb0, v3 = d[j][3] + cb1;
            float sc0 = v0, sc1 = v1, qc0 = v0*v0, qc1 = v1*v1;
            *(float2*)&g_x1[(size_t)(b*NT + rA)*NH1 + c0] = make_float2(v0, v1);
            if (okB) {
                *(float2*)&g_x1[(size_t)(b*NT + rB)*NH1 + c0] = make_float2(v2, v3);
                sc0 += v2; sc1 += v3; qc0 += v2*v2; qc1 += v3*v3;
            }
            #pragma unroll
            for (int off = 4; off <= 16; off <<= 1) {
                sc0 += __shfl_xor_sync(0xffffffffu, sc0, off);
                sc1 += __shfl_xor_sync(0xffffffffu, sc1, off);
                qc0 += __shfl_xor_sync(0xffffffffu, qc0, off);
                qc1 += __shfl_xor_sync(0xffffffffu, qc1, off);
            }
            if (lane < 4) {
                atomicAdd(&s_sum[c0],   sc0); atomicAdd(&s_sum[c0+1], sc1);
                atomicAdd(&s_sq[c0],    qc0); atomicAdd(&s_sq[c0+1],  qc1);
            }
        }
    }
    __syncthreads();
    if (tid < NH1) {
        atomicAdd(&g_sum1[tid], s_sum[tid]);
        atomicAdd(&g_sq1[tid],  s_sq[tid]);
    }
}

// ---------------------------------------------------------------------------
// Kernel B: x2 = dice1(x1) @ W2 + b2 via 3xTF32 mma.sync; layer-2 stats.
// fin1 folded into prologue. 128 rows/block, 256 threads, 8 warps.
// ---------------------------------------------------------------------------
__global__ __launch_bounds__(256, 4) void k_gemm2(
    const float* __restrict__ W2, const float* __restrict__ b2,
    const float* __restrict__ alpha1)
{
    __shared__ __align__(16) float s_x[128*68];     // fp32 dice1(x1) tile
    __shared__ float s_W2TH[16*68], s_W2TL[16*68];  // W2^T hi/lo [n][k]
    __shared__ float s_m1[64], s_r1[64], s_a1[64], s_b2[16];
    __shared__ float s_sum[16], s_sq[16];

    int tid = threadIdx.x;
    int row0 = blockIdx.x * 128;
    if (tid < 64) {
        float n = (float)NROWS;
        float m = g_sum1[tid] / n;
        float v = g_sq1[tid] / n - m*m;
        s_m1[tid] = m;
        s_r1[tid] = rsqrtf(v + 1e-8f);
        s_a1[tid] = alpha1[tid];
    }
    if (tid < 16) { s_b2[tid] = b2[tid]; s_sum[tid] = 0.f; s_sq[tid] = 0.f; }
    #pragma unroll
    for (int i = 0; i < 4; i++) {
        int idx = tid + 256*i;
        int k = idx >> 4, n = idx & 15;
        float wv = W2[idx];
        unsigned wh, wl; tf32_split(wv, wh, wl);
        s_W2TH[n*68 + k] = __uint_as_float(wh);
        s_W2TL[n*68 + k] = __uint_as_float(wl);
    }
    __syncthreads();

    // stage 128x64 x1 tile with dice1 applied (batched LDGs for MLP)
    #pragma unroll
    for (int bt = 0; bt < 4; bt++) {
        float4 vr[2];
        int f4b = tid + 256*(bt*2);
        #pragma unroll
        for (int u = 0; u < 2; u++) {
            int f4 = f4b + 256*u;
            int r = f4 >> 4, e0 = (f4 & 15) << 2;
            vr[u] = *(const float4*)&g_x1[(size_t)(row0 + r)*64 + e0];
        }
        #pragma unroll
        for (int u = 0; u < 2; u++) {
            int f4 = f4b + 256*u;
            int r = f4 >> 4, e0 = (f4 & 15) << 2;
            float vv[4] = {vr[u].x, vr[u].y, vr[u].z, vr[u].w};
            #pragma unroll
            for (int uu = 0; uu < 4; uu++) {
                int j = e0 + uu;
                float xn = (vv[uu] - s_m1[j]) * s_r1[j];
                float p  = __fdividef(1.f, 1.f + __expf(-xn));
                float a  = s_a1[j];
                vv[uu] = vv[uu] * (a + (1.f - a) * p);
            }
            *(float4*)&s_x[r*68 + e0] = make_float4(vv[0], vv[1], vv[2], vv[3]);
        }
    }
    __syncthreads();

    int w = tid >> 5, lane = tid & 31, g = lane >> 2, tin = lane & 3;
    float d[2][4];
    #pragma unroll
    for (int n = 0; n < 2; n++)
        #pragma unroll
        for (int u = 0; u < 4; u++) d[n][u] = 0.f;

    int arow = (16*w + g)*68;
    #pragma unroll
    for (int kt = 0; kt < 8; kt++) {
        int k0 = kt*8;
        float a0f = s_x[arow + k0 + tin];
        float a1f = s_x[arow + 8*68 + k0 + tin];
        float a2f = s_x[arow + k0 + tin + 4];
        float a3f = s_x[arow + 8*68 + k0 + tin + 4];
        unsigned ah0,ah1,ah2,ah3, al0,al1,al2,al3;
        tf32_split(a0f, ah0, al0); tf32_split(a1f, ah1, al1);
        tf32_split(a2f, ah2, al2); tf32_split(a3f, ah3, al3);
        #pragma unroll
        for (int n = 0; n < 2; n++) {
            int bbase = (n*8 + g)*68 + k0 + tin;
            unsigned bh0 = __float_as_uint(s_W2TH[bbase]);
            unsigned bh1 = __float_as_uint(s_W2TH[bbase + 4]);
            unsigned bl0 = __float_as_uint(s_W2TL[bbase]);
            unsigned bl1 = __float_as_uint(s_W2TL[bbase + 4]);
            MMA_TF32(d[n], ah0,ah1,ah2,ah3, bh0,bh1);
            MMA_TF32(d[n], ah0,ah1,ah2,ah3, bl0,bl1);
            MMA_TF32(d[n], al0,al1,al2,al3, bh0,bh1);
        }
    }

    int rA = 16*w + g, rB = rA + 8;
    #pragma unroll
    for (int n = 0; n < 2; n++) {
        int c0 = n*8 + tin*2;
        float b0v = s_b2[c0], b1v = s_b2[c0+1];
        float v0 = d[n][0] + b0v, v1 = d[n][1] + b1v;
        float v2 = d[n][2] + b0v, v3 = d[n][3] + b1v;
        *(float2*)&g_x2[(size_t)(row0 + rA)*16 + c0] = make_float2(v0, v1);
        *(float2*)&g_x2[(size_t)(row0 + rB)*16 + c0] = make_float2(v2, v3);
        float sc0 = v0 + v2, sc1 = v1 + v3;
        float qc0 = v0*v0 + v2*v2, qc1 = v1*v1 + v3*v3;
        #pragma unroll
        for (int off = 4; off <= 16; off <<= 1) {
            sc0 += __shfl_xor_sync(0xffffffffu, sc0, off);
            sc1 += __shfl_xor_sync(0xffffffffu, sc1, off);
            qc0 += __shfl_xor_sync(0xffffffffu, qc0, off);
            qc1 += __shfl_xor_sync(0xffffffffu, qc1, off);
        }
        if (lane < 4) {
            atomicAdd(&s_sum[c0],   sc0); atomicAdd(&s_sum[c0+1], sc1);
            atomicAdd(&s_sq[c0],    qc0); atomicAdd(&s_sq[c0+1],  qc1);
        }
    }
    __syncthreads();
    if (tid < 16) {
        atomicAdd(&g_sum2[tid], s_sum[tid]);
        atomicAdd(&g_sq2[tid],  s_sq[tid]);
    }
}

// ---------------------------------------------------------------------------
// Kernel C: dice2 -> mask -> softmax over T -> score @ hist (3xTF32 MMA) -> out
// One block per batch; fin2 folded into prologue.
// ---------------------------------------------------------------------------
__global__ __launch_bounds__(256, 4) void k_final(
    const float* __restrict__ hist, const int* __restrict__ lens,
    const float* __restrict__ alpha2, float* __restrict__ out)
{
    __shared__ __align__(16) float s_logit[200][20];   // dice2-masked logits [t][h]
    __shared__ __align__(16) float s_p[16][204];       // exp values [h][t]
    __shared__ __align__(16) float s_hist[64][72];     // hist chunk [t][e]
    __shared__ float s_inv[16];
    __shared__ float s_m2[16], s_r2[16], s_a2[16];

    int b = blockIdx.x, tid = threadIdx.x;
    if (tid < 16) {
        float n = (float)NROWS;
        float m = g_sum2[tid] / n;
        float v = g_sq2[tid] / n - m*m;
        s_m2[tid] = m;
        s_r2[tid] = rsqrtf(v + 1e-8f);
        s_a2[tid] = alpha2[tid];
    }
    __syncthreads();
    int len = lens[b];

    // stage logits with dice2 + mask (mask: t < len -> 1e-9)
    #pragma unroll
    for (int i = 0; i < 4; i++) {
        int f4 = tid + 256*i;
        if (f4 < 800) {
            int r = f4 >> 2, h0 = (f4 & 3) << 2;
            float4 v = *(const float4*)&g_x2[(size_t)(b*NT + r)*16 + h0];
            float vv[4] = {v.x, v.y, v.z, v.w};
            #pragma unroll
            for (int u = 0; u < 4; u++) {
                int hh = h0 + u;
                float xn = (vv[u] - s_m2[hh]) * s_r2[hh];
                float p  = __fdividef(1.f, 1.f + __expf(-xn));
                float a  = s_a2[hh];
                float dd = vv[u] * (a + (1.f - a) * p);
                vv[u] = (r < len) ? 1e-9f : dd;
            }
            *(float4*)&s_logit[r][h0] = make_float4(vv[0], vv[1], vv[2], vv[3]);
        }
    }
    __syncthreads();

    // 16 softmaxes over T=200 (one per half-warp-of-16); exp -> s_p[h][t]
    int g = tid >> 4, l16 = tid & 15;
    float m = -1e30f;
    for (int t = l16; t < NT; t += 16) m = fmaxf(m, s_logit[t][g]);
    #pragma unroll
    for (int off = 1; off < 16; off <<= 1)
        m = fmaxf(m, __shfl_xor_sync(0xffffffffu, m, off, 16));
    float s = 0.f;
    for (int t = l16; t < NT; t += 16) {
        float ev = __expf(s_logit[t][g] - m);
        s_p[g][t] = ev;
        s += ev;
    }
    #pragma unroll
    for (int off = 1; off < 16; off <<= 1)
        s += __shfl_xor_sync(0xffffffffu, s, off, 16);
    if (l16 == 0) s_inv[g] = __fdividef(1.f, s);

    // out[b,:,:] = (1/sum) * p[16x200] @ hist[200x64]   via 3xTF32 MMA
    int w = tid >> 5, lane = tid & 31, gq = lane >> 2, tin = lane & 3;
    int n0 = w * 8;
    float d[4] = {0.f, 0.f, 0.f, 0.f};

    for (int ck = 0; ck < 4; ck++) {
        __syncthreads();
        int rows = (ck < 3) ? 64 : 8;
        for (int f4 = tid; f4 < rows*16; f4 += 256) {
            int r = f4 >> 4, e0 = (f4 & 15) << 2;
            *(float4*)&s_hist[r][e0] =
                *(const float4*)&hist[(size_t)(b*NT + ck*64 + r)*64 + e0];
        }
        __syncthreads();
        int kts = rows >> 3;
        for (int kt = 0; kt < kts; kt++) {
            int k0 = kt*8, gk = ck*64 + k0;
            float a0f = s_p[gq][gk + tin];
            float a1f = s_p[gq+8][gk + tin];
            float a2f = s_p[gq][gk + tin + 4];
            float a3f = s_p[gq+8][gk + tin + 4];
            unsigned ah0,ah1,ah2,ah3, al0,al1,al2,al3;
            tf32_split(a0f, ah0, al0); tf32_split(a1f, ah1, al1);
            tf32_split(a2f, ah2, al2); tf32_split(a3f, ah3, al3);
            float b0f = s_hist[k0 + tin][n0 + gq];
            float b1f = s_hist[k0 + tin + 4][n0 + gq];
            unsigned bh0,bl0,bh1,bl1;
            tf32_split(b0f, bh0, bl0); tf32_split(b1f, bh1, bl1);
            MMA_TF32(d, ah0,ah1,ah2,ah3, bh0,bh1);
            MMA_TF32(d, ah0,ah1,ah2,ah3, bl0,bl1);
            MMA_TF32(d, al0,al1,al2,al3, bh0,bh1);
        }
    }

    // epilogue: scale by 1/sum per h row, write out
    float i0 = s_inv[gq], i1 = s_inv[gq + 8];
    int e0 = n0 + tin*2;
    *(float2*)&out[(size_t)(b*NH2 + gq    )*NE + e0] = make_float2(d[0]*i0, d[1]*i0);
    *(float2*)&out[(size_t)(b*NH2 + gq + 8)*NE + e0] = make_float2(d[2]*i1, d[3]*i1);
}

extern "C" void kernel_launch(void* const* d_in, const int* in_sizes, int n_in,
                              void* d_out, int out_size)
{
    const float* q    = (const float*)d_in[0];
    const float* hist = (const float*)d_in[1];
    const int*   lens = (const int*)  d_in[2];
    const float* W1   = (const float*)d_in[3];
    const float* b1   = (const float*)d_in[4];
    const float* a1   = (const float*)d_in[5];
    const float* W2   = (const float*)d_in[6];
    const float* b2   = (const float*)d_in[7];
    const float* a2   = (const float*)d_in[8];
    float* out = (float*)d_out;

    const int dyn1 = (128*68 + 2*64*72) * 4;   // 71680 B
    static int s_attr_done = 0;
    if (!s_attr_done) {
        cudaFuncSetAttribute(k_gemm1, cudaFuncAttributeMaxDynamicSharedMemorySize, dyn1);
        s_attr_done = 1;
    }

    k_zero<<<1, 64>>>();
    k_gemm1<<<2*NB, 256, dyn1>>>(q, hist, W1, b1);
    k_gemm2<<<NROWS/128, 256>>>(W2, b2, a1);
    k_final<<<NB, 256>>>(hist, lens, a2, out);
}